// round 1
// baseline (speedup 1.0000x reference)
#include <cuda_runtime.h>
#include <math.h>
#include <float.h>

#define SEQ    2048
#define DMODEL 2048
#define NH     16
#define DH     128
#define QKV_N  6144

// Scratch (allocation-free rule: __device__ globals)
__device__ __align__(16) float g_qkv[SEQ * QKV_N];     // [s, 3d]  (Q|K|V)
__device__ __align__(16) float g_attn[SEQ * DMODEL];   // [s, h*dh]

// ---------------------------------------------------------------------------
// Tiled SGEMM with bias: C[M,N] = A[M,K] @ B[K,N] + bias[N]
// BM=BN=128, BK=16, 256 threads, 8x8 per-thread micro-tile.
// ---------------------------------------------------------------------------
#define BM 128
#define BN 128
#define BK 16
#define TM 8
#define TN 8

__global__ __launch_bounds__(256) void sgemm_bias(
    const float* __restrict__ A, const float* __restrict__ B,
    const float* __restrict__ bias, float* __restrict__ C,
    int M, int N, int K)
{
    __shared__ float As[BK][BM];   // A stored transposed: As[k][m]
    __shared__ float Bs[BK][BN];

    const int tid  = threadIdx.x;
    const int row0 = blockIdx.y * BM;
    const int col0 = blockIdx.x * BN;

    const int rm = tid >> 4;   // 0..15
    const int rn = tid & 15;   // 0..15

    // A tile load mapping: 128 rows x 4 float4 (16 cols)
    const int aRow = tid >> 2;         // 0..63 (+64)
    const int aCol = (tid & 3) * 4;    // 0,4,8,12
    // B tile load mapping: 16 rows x 32 float4 (128 cols)
    const int bRow = tid >> 5;         // 0..7 (+8)
    const int bCol = (tid & 31) * 4;

    float acc[TM][TN];
    #pragma unroll
    for (int i = 0; i < TM; i++)
        #pragma unroll
        for (int j = 0; j < TN; j++) acc[i][j] = 0.f;

    for (int kt = 0; kt < K; kt += BK) {
        #pragma unroll
        for (int r = 0; r < 2; r++) {
            int row = aRow + r * 64;
            float4 v = *reinterpret_cast<const float4*>(
                &A[(size_t)(row0 + row) * K + kt + aCol]);
            As[aCol + 0][row] = v.x;
            As[aCol + 1][row] = v.y;
            As[aCol + 2][row] = v.z;
            As[aCol + 3][row] = v.w;
        }
        #pragma unroll
        for (int r = 0; r < 2; r++) {
            int row = bRow + r * 8;
            float4 v = *reinterpret_cast<const float4*>(
                &B[(size_t)(kt + row) * N + col0 + bCol]);
            *reinterpret_cast<float4*>(&Bs[row][bCol]) = v;
        }
        __syncthreads();

        #pragma unroll
        for (int k = 0; k < BK; k++) {
            float a[TM], b[TN];
            #pragma unroll
            for (int i = 0; i < TM; i += 4)
                *reinterpret_cast<float4*>(&a[i]) =
                    *reinterpret_cast<const float4*>(&As[k][rm * TM + i]);
            #pragma unroll
            for (int j = 0; j < TN; j += 4)
                *reinterpret_cast<float4*>(&b[j]) =
                    *reinterpret_cast<const float4*>(&Bs[k][rn * TN + j]);
            #pragma unroll
            for (int i = 0; i < TM; i++)
                #pragma unroll
                for (int j = 0; j < TN; j++)
                    acc[i][j] += a[i] * b[j];
        }
        __syncthreads();
    }

    #pragma unroll
    for (int i = 0; i < TM; i++) {
        int row = row0 + rm * TM + i;
        #pragma unroll
        for (int j = 0; j < TN; j++) {
            int col = col0 + rn * TN + j;
            C[(size_t)row * N + col] = acc[i][j] + bias[col];
        }
    }
}

// ---------------------------------------------------------------------------
// Flash attention (fp32, causal, additive per-head key bias).
// Grid: (q_blocks=32, heads=16), 256 threads (8 warps), BM=BN=64, DH=128.
// Each warp owns 8 query rows; lane j handles keys {j, j+32} for scores.
// K is staged transposed in smem for conflict-free score loads.
// ---------------------------------------------------------------------------
#define FB_M 64
#define FB_N 64
#define FLASH_SMEM ((FB_M * DH + DH * FB_N + FB_M * DH) * 4)

__global__ __launch_bounds__(256) void flash_attn(
    const float* __restrict__ qkv, const float* __restrict__ attn_bias,
    float* __restrict__ out)
{
    extern __shared__ float sm[];
    float* Q_s  = sm;                    // [64][128]
    float* Kt_s = Q_s + FB_M * DH;       // [128][64]
    float* V_s  = Kt_s + DH * FB_N;      // [64][128]
    __shared__ float p_s[8][FB_N];

    const int qb   = blockIdx.x;
    const int h    = blockIdx.y;
    const int tid  = threadIdx.x;
    const int warp = tid >> 5;
    const int lane = tid & 31;

    const float scale = 0.08838834764831845f;  // 1/sqrt(128)
    const float* biash = attn_bias + (size_t)h * SEQ;

    // Load Q tile (64 x 128)
    #pragma unroll
    for (int it = 0; it < 8; it++) {
        int idx = tid + it * 256;   // float4 index, 32 per row
        int row = idx >> 5;
        int c4  = (idx & 31) * 4;
        float4 v = *reinterpret_cast<const float4*>(
            &qkv[(size_t)(qb * FB_M + row) * QKV_N + h * DH + c4]);
        *reinterpret_cast<float4*>(&Q_s[row * DH + c4]) = v;
    }

    float m_i[8], l_i[8], o_acc[8][4];
    #pragma unroll
    for (int r = 0; r < 8; r++) {
        m_i[r] = -1e30f; l_i[r] = 0.f;
        #pragma unroll
        for (int t = 0; t < 4; t++) o_acc[r][t] = 0.f;
    }

    for (int kb = 0; kb <= qb; kb++) {
        __syncthreads();   // previous iteration's consumers done
        // Load K block transposed, V block natural
        #pragma unroll
        for (int it = 0; it < 8; it++) {
            int idx = tid + it * 256;
            int j   = idx >> 5;
            int c4  = (idx & 31) * 4;
            float4 kv = *reinterpret_cast<const float4*>(
                &qkv[(size_t)(kb * FB_N + j) * QKV_N + DMODEL + h * DH + c4]);
            Kt_s[(c4 + 0) * FB_N + j] = kv.x;
            Kt_s[(c4 + 1) * FB_N + j] = kv.y;
            Kt_s[(c4 + 2) * FB_N + j] = kv.z;
            Kt_s[(c4 + 3) * FB_N + j] = kv.w;
            float4 vv = *reinterpret_cast<const float4*>(
                &qkv[(size_t)(kb * FB_N + j) * QKV_N + 2 * DMODEL + h * DH + c4]);
            *reinterpret_cast<float4*>(&V_s[j * DH + c4]) = vv;
        }
        __syncthreads();   // tiles ready (also covers Q on first iter)

        const bool diag = (kb == qb);
        #pragma unroll
        for (int rr = 0; rr < 8; rr++) {
            int r_loc = warp * 8 + rr;
            int qrow  = qb * FB_M + r_loc;

            float s0 = 0.f, s1 = 0.f;
            const float* qrow_s = &Q_s[r_loc * DH];
            #pragma unroll 4
            for (int d = 0; d < DH; d++) {
                float qv = qrow_s[d];
                s0 += qv * Kt_s[d * FB_N + lane];
                s1 += qv * Kt_s[d * FB_N + lane + 32];
            }
            int j0 = kb * FB_N + lane;
            int j1 = j0 + 32;
            s0 = s0 * scale + biash[j0];
            s1 = s1 * scale + biash[j1];
            if (diag) {
                if (j0 > qrow) s0 = -1e30f;
                if (j1 > qrow) s1 = -1e30f;
            }

            float mx = fmaxf(s0, s1);
            #pragma unroll
            for (int off = 16; off > 0; off >>= 1)
                mx = fmaxf(mx, __shfl_xor_sync(0xffffffffu, mx, off));
            float m_new = fmaxf(m_i[rr], mx);

            float p0 = __expf(s0 - m_new);
            float p1 = __expf(s1 - m_new);
            float ps = p0 + p1;
            #pragma unroll
            for (int off = 16; off > 0; off >>= 1)
                ps += __shfl_xor_sync(0xffffffffu, ps, off);

            float alpha = __expf(m_i[rr] - m_new);
            l_i[rr] = l_i[rr] * alpha + ps;
            m_i[rr] = m_new;

            p_s[warp][lane]      = p0;
            p_s[warp][lane + 32] = p1;
            __syncwarp();

            #pragma unroll
            for (int t = 0; t < 4; t++) {
                int d = lane + 32 * t;
                float acc = 0.f;
                #pragma unroll 8
                for (int j = 0; j < FB_N; j++)
                    acc += p_s[warp][j] * V_s[j * DH + d];
                o_acc[rr][t] = o_acc[rr][t] * alpha + acc;
            }
            __syncwarp();   // before next rr overwrites p_s
        }
    }

    // Epilogue: normalize and write [s, h*dh]
    #pragma unroll
    for (int rr = 0; rr < 8; rr++) {
        int r_loc = warp * 8 + rr;
        int qrow  = qb * FB_M + r_loc;
        float inv = 1.f / l_i[rr];
        #pragma unroll
        for (int t = 0; t < 4; t++)
            out[(size_t)qrow * DMODEL + h * DH + lane + 32 * t] = o_acc[rr][t] * inv;
    }
}

// ---------------------------------------------------------------------------
// kernel_launch
// Inputs (metadata order): x, Wqkv, Wqkv_bias, out_w, out_b, attn_bias,
//                          key_padding_mask (all-True for this problem; no-op)
// ---------------------------------------------------------------------------
extern "C" void kernel_launch(void* const* d_in, const int* in_sizes, int n_in,
                              void* d_out, int out_size)
{
    (void)in_sizes; (void)n_in; (void)out_size;
    const float* x         = (const float*)d_in[0];
    const float* Wqkv      = (const float*)d_in[1];
    const float* Wqkv_bias = (const float*)d_in[2];
    const float* out_w     = (const float*)d_in[3];
    const float* out_b     = (const float*)d_in[4];
    const float* attn_bias = (const float*)d_in[5];
    float* out = (float*)d_out;

    float* qkv  = nullptr;
    float* attn = nullptr;
    cudaGetSymbolAddress((void**)&qkv,  g_qkv);
    cudaGetSymbolAddress((void**)&attn, g_attn);

    // 1) QKV projection: [2048,2048] @ [2048,6144] + bias
    sgemm_bias<<<dim3(QKV_N / BN, SEQ / BM), 256>>>(
        x, Wqkv, Wqkv_bias, qkv, SEQ, QKV_N, DMODEL);

    // 2) Flash attention (causal + per-head key bias)
    cudaFuncSetAttribute(flash_attn,
                         cudaFuncAttributeMaxDynamicSharedMemorySize, FLASH_SMEM);
    flash_attn<<<dim3(SEQ / FB_M, NH), 256, FLASH_SMEM>>>(qkv, attn_bias, attn);

    // 3) Output projection: [2048,2048] @ [2048,2048] + bias
    sgemm_bias<<<dim3(DMODEL / BN, SEQ / BM), 256>>>(
        attn, out_w, out_b, out, SEQ, DMODEL, DMODEL);
}

// round 2
// speedup vs baseline: 5.4339x; 5.4339x over previous
#include <cuda_runtime.h>
#include <math.h>
#include <stdint.h>

#define SEQ    2048
#define DMODEL 2048
#define NH     16
#define DH     128
#define QKV_N  6144

// Scratch (allocation-free rule: __device__ globals)
__device__ __align__(16) float g_qkv[SEQ * QKV_N];     // [s, 3d]  (Q|K|V)
__device__ __align__(16) float g_attn[SEQ * DMODEL];   // [s, h*dh]

// ---------------------------------------------------------------------------
// tf32 helpers
// ---------------------------------------------------------------------------
__device__ __forceinline__ uint32_t f2tf32(float x) {
    uint32_t r;
    asm("cvt.rna.tf32.f32 %0, %1;" : "=r"(r) : "f"(x));
    return r;
}

// D += A(16x8) * B(8x8), tf32 in, fp32 accumulate
__device__ __forceinline__ void mma_tf32(float c[4], const uint32_t a[4],
                                         uint32_t b0, uint32_t b1) {
    asm volatile(
        "mma.sync.aligned.m16n8k8.row.col.f32.tf32.tf32.f32 "
        "{%0,%1,%2,%3}, {%4,%5,%6,%7}, {%8,%9}, {%0,%1,%2,%3};"
        : "+f"(c[0]), "+f"(c[1]), "+f"(c[2]), "+f"(c[3])
        : "r"(a[0]), "r"(a[1]), "r"(a[2]), "r"(a[3]), "r"(b0), "r"(b1));
}

// ---------------------------------------------------------------------------
// TF32 tensor-core GEMM: C[M,N] = A[M,K] @ B[K,N] + bias[N]
// BM=128, BN=128, BK=32, 256 threads (8 warps, 4m x 2n), warp tile 32x64.
// ---------------------------------------------------------------------------
#define GBM 128
#define GBN 128
#define GBK 32
#define ASTRIDE (GBK + 4)   // 36: 36%32=4 -> a-frag banks 4r+k unique
#define BSTRIDE (GBN + 8)   // 136: 136%32=8 -> b-frag banks 8k+n unique

__global__ __launch_bounds__(256) void gemm_tf32(
    const float* __restrict__ A, const float* __restrict__ B,
    const float* __restrict__ bias, float* __restrict__ C,
    int M, int N, int K)
{
    __shared__ uint32_t As[GBM * ASTRIDE];
    __shared__ uint32_t Bs[GBK * BSTRIDE];

    const int tid  = threadIdx.x;
    const int warp = tid >> 5;
    const int lane = tid & 31;
    const int gq   = lane >> 2;   // group id 0..7
    const int kq   = lane & 3;    // thread-in-group 0..3
    const int wm   = warp >> 1;   // 0..3  -> row offset wm*32
    const int wn   = warp & 1;    // 0..1  -> col offset wn*64
    const int row0 = blockIdx.y * GBM;
    const int col0 = blockIdx.x * GBN;

    float acc[2][8][4];
    #pragma unroll
    for (int mt = 0; mt < 2; mt++)
        #pragma unroll
        for (int nt = 0; nt < 8; nt++)
            #pragma unroll
            for (int i = 0; i < 4; i++) acc[mt][nt][i] = 0.f;

    for (int kt = 0; kt < K; kt += GBK) {
        // A tile 128x32
        #pragma unroll
        for (int i = 0; i < 4; i++) {
            int idx = tid + i * 256;
            int r = idx >> 3, c = (idx & 7) * 4;
            float4 v = *reinterpret_cast<const float4*>(
                &A[(size_t)(row0 + r) * K + kt + c]);
            As[r * ASTRIDE + c + 0] = f2tf32(v.x);
            As[r * ASTRIDE + c + 1] = f2tf32(v.y);
            As[r * ASTRIDE + c + 2] = f2tf32(v.z);
            As[r * ASTRIDE + c + 3] = f2tf32(v.w);
        }
        // B tile 32x128
        #pragma unroll
        for (int i = 0; i < 4; i++) {
            int idx = tid + i * 256;
            int r = idx >> 5, c = (idx & 31) * 4;
            float4 v = *reinterpret_cast<const float4*>(
                &B[(size_t)(kt + r) * N + col0 + c]);
            Bs[r * BSTRIDE + c + 0] = f2tf32(v.x);
            Bs[r * BSTRIDE + c + 1] = f2tf32(v.y);
            Bs[r * BSTRIDE + c + 2] = f2tf32(v.z);
            Bs[r * BSTRIDE + c + 3] = f2tf32(v.w);
        }
        __syncthreads();

        #pragma unroll
        for (int ks = 0; ks < 4; ks++) {
            const int k0 = ks * 8;
            uint32_t af[2][4];
            #pragma unroll
            for (int mt = 0; mt < 2; mt++) {
                int m = wm * 32 + mt * 16;
                af[mt][0] = As[(m + gq) * ASTRIDE + k0 + kq];
                af[mt][1] = As[(m + gq + 8) * ASTRIDE + k0 + kq];
                af[mt][2] = As[(m + gq) * ASTRIDE + k0 + kq + 4];
                af[mt][3] = As[(m + gq + 8) * ASTRIDE + k0 + kq + 4];
            }
            #pragma unroll
            for (int nt = 0; nt < 8; nt++) {
                int n = wn * 64 + nt * 8;
                uint32_t b0 = Bs[(k0 + kq) * BSTRIDE + n + gq];
                uint32_t b1 = Bs[(k0 + kq + 4) * BSTRIDE + n + gq];
                mma_tf32(acc[0][nt], af[0], b0, b1);
                mma_tf32(acc[1][nt], af[1], b0, b1);
            }
        }
        __syncthreads();
    }

    #pragma unroll
    for (int mt = 0; mt < 2; mt++) {
        int m = row0 + wm * 32 + mt * 16 + gq;
        #pragma unroll
        for (int nt = 0; nt < 8; nt++) {
            int n = col0 + wn * 64 + nt * 8 + kq * 2;
            float b0v = bias[n], b1v = bias[n + 1];
            float2 r0 = make_float2(acc[mt][nt][0] + b0v, acc[mt][nt][1] + b1v);
            float2 r1 = make_float2(acc[mt][nt][2] + b0v, acc[mt][nt][3] + b1v);
            *reinterpret_cast<float2*>(&C[(size_t)m * N + n]) = r0;
            *reinterpret_cast<float2*>(&C[(size_t)(m + 8) * N + n]) = r1;
        }
    }
}

// ---------------------------------------------------------------------------
// Flash attention with tf32 MMA (causal + per-head additive key bias).
// BM=128 q-rows, BN=64 keys, DH=128. 8 warps, each owns 16 complete q-rows
// (softmax reductions stay within the warp: 4 lanes per row pair).
// ---------------------------------------------------------------------------
#define FM 128
#define FN 64
#define QSTR (DH + 4)    // 132: a-frag / K b-frag conflict-free (4r+k)
#define KSTR (DH + 4)    // 132
#define VSTR (DH + 8)    // 136: V b-frag conflict-free (8k+n)
#define PSTR (FN + 4)    // 68:  P a-frag conflict-free (4r+k)
#define FLASH_SMEM ((FM * QSTR + FN * KSTR + FN * VSTR + FM * PSTR) * 4)

__global__ __launch_bounds__(256) void flash_tf32(
    const float* __restrict__ qkv, const float* __restrict__ attn_bias,
    float* __restrict__ out)
{
    extern __shared__ uint32_t sm[];
    uint32_t* Qs = sm;                     // [128][132]
    uint32_t* Ks = Qs + FM * QSTR;         // [64][132]
    uint32_t* Vs = Ks + FN * KSTR;         // [64][136]
    uint32_t* Ps = Vs + FN * VSTR;         // [128][68]

    const int qb   = (gridDim.x - 1) - blockIdx.x;  // heavy blocks first
    const int h    = blockIdx.y;
    const int tid  = threadIdx.x;
    const int warp = tid >> 5;
    const int lane = tid & 31;
    const int gq   = lane >> 2;
    const int kq   = lane & 3;

    const float scale = 0.08838834764831845f;  // 1/sqrt(128)
    const float* bh = attn_bias + (size_t)h * SEQ;

    // Load Q tile (128 x 128) -> tf32
    #pragma unroll
    for (int i = 0; i < 16; i++) {
        int idx = tid + i * 256;
        int r = idx >> 5, c = (idx & 31) * 4;
        float4 v = *reinterpret_cast<const float4*>(
            &qkv[(size_t)(qb * FM + r) * QKV_N + h * DH + c]);
        Qs[r * QSTR + c + 0] = f2tf32(v.x);
        Qs[r * QSTR + c + 1] = f2tf32(v.y);
        Qs[r * QSTR + c + 2] = f2tf32(v.z);
        Qs[r * QSTR + c + 3] = f2tf32(v.w);
    }

    float o[16][4];
    #pragma unroll
    for (int nt = 0; nt < 16; nt++)
        #pragma unroll
        for (int i = 0; i < 4; i++) o[nt][i] = 0.f;
    float m0 = -1e30f, m1 = -1e30f, l0 = 0.f, l1 = 0.f;

    const int qrow0 = qb * FM + warp * 16 + gq;   // row of c0/c1
    const int nkb = 2 * qb + 2;

    for (int kb = 0; kb < nkb; kb++) {
        __syncthreads();   // prior consumers of Ks/Vs/Ps done
        // Load K, V blocks (64 x 128 each) -> tf32
        #pragma unroll
        for (int i = 0; i < 8; i++) {
            int idx = tid + i * 256;
            int r = idx >> 5, c = (idx & 31) * 4;
            const float* kp = &qkv[(size_t)(kb * FN + r) * QKV_N + DMODEL + h * DH + c];
            float4 kv = *reinterpret_cast<const float4*>(kp);
            Ks[r * KSTR + c + 0] = f2tf32(kv.x);
            Ks[r * KSTR + c + 1] = f2tf32(kv.y);
            Ks[r * KSTR + c + 2] = f2tf32(kv.z);
            Ks[r * KSTR + c + 3] = f2tf32(kv.w);
            float4 vv = *reinterpret_cast<const float4*>(kp + DMODEL);
            Vs[r * VSTR + c + 0] = f2tf32(vv.x);
            Vs[r * VSTR + c + 1] = f2tf32(vv.y);
            Vs[r * VSTR + c + 2] = f2tf32(vv.z);
            Vs[r * VSTR + c + 3] = f2tf32(vv.w);
        }
        __syncthreads();

        // ---- Scores: S(16x64) = Q(16x128) @ K^T per warp ----
        float s[8][4];
        #pragma unroll
        for (int nt = 0; nt < 8; nt++)
            #pragma unroll
            for (int i = 0; i < 4; i++) s[nt][i] = 0.f;

        #pragma unroll
        for (int ks = 0; ks < 16; ks++) {
            const int k0 = ks * 8;
            uint32_t a[4];
            a[0] = Qs[(warp * 16 + gq) * QSTR + k0 + kq];
            a[1] = Qs[(warp * 16 + gq + 8) * QSTR + k0 + kq];
            a[2] = Qs[(warp * 16 + gq) * QSTR + k0 + kq + 4];
            a[3] = Qs[(warp * 16 + gq + 8) * QSTR + k0 + kq + 4];
            #pragma unroll
            for (int nt = 0; nt < 8; nt++) {
                uint32_t b0 = Ks[(nt * 8 + gq) * KSTR + k0 + kq];
                uint32_t b1 = Ks[(nt * 8 + gq) * KSTR + k0 + kq + 4];
                mma_tf32(s[nt], a, b0, b1);
            }
        }

        // ---- bias + scale + causal mask ----
        const bool diag = (kb >= 2 * qb);
        #pragma unroll
        for (int nt = 0; nt < 8; nt++) {
            int j = nt * 8 + kq * 2;
            float b0v = bh[kb * FN + j], b1v = bh[kb * FN + j + 1];
            s[nt][0] = s[nt][0] * scale + b0v;
            s[nt][1] = s[nt][1] * scale + b1v;
            s[nt][2] = s[nt][2] * scale + b0v;
            s[nt][3] = s[nt][3] * scale + b1v;
            if (diag) {
                int jg = kb * FN + j;
                if (jg     > qrow0)     s[nt][0] = -1e30f;
                if (jg + 1 > qrow0)     s[nt][1] = -1e30f;
                if (jg     > qrow0 + 8) s[nt][2] = -1e30f;
                if (jg + 1 > qrow0 + 8) s[nt][3] = -1e30f;
            }
        }

        // ---- online softmax (rows split across 4 lanes of same group) ----
        float mx0 = -1e30f, mx1 = -1e30f;
        #pragma unroll
        for (int nt = 0; nt < 8; nt++) {
            mx0 = fmaxf(mx0, fmaxf(s[nt][0], s[nt][1]));
            mx1 = fmaxf(mx1, fmaxf(s[nt][2], s[nt][3]));
        }
        mx0 = fmaxf(mx0, __shfl_xor_sync(0xffffffffu, mx0, 1));
        mx0 = fmaxf(mx0, __shfl_xor_sync(0xffffffffu, mx0, 2));
        mx1 = fmaxf(mx1, __shfl_xor_sync(0xffffffffu, mx1, 1));
        mx1 = fmaxf(mx1, __shfl_xor_sync(0xffffffffu, mx1, 2));

        float mn0 = fmaxf(m0, mx0), mn1 = fmaxf(m1, mx1);
        float al0 = __expf(m0 - mn0), al1 = __expf(m1 - mn1);
        m0 = mn0; m1 = mn1;

        float ps0 = 0.f, ps1 = 0.f;
        #pragma unroll
        for (int nt = 0; nt < 8; nt++) {
            s[nt][0] = __expf(s[nt][0] - mn0);
            s[nt][1] = __expf(s[nt][1] - mn0);
            s[nt][2] = __expf(s[nt][2] - mn1);
            s[nt][3] = __expf(s[nt][3] - mn1);
            ps0 += s[nt][0] + s[nt][1];
            ps1 += s[nt][2] + s[nt][3];
        }
        ps0 += __shfl_xor_sync(0xffffffffu, ps0, 1);
        ps0 += __shfl_xor_sync(0xffffffffu, ps0, 2);
        ps1 += __shfl_xor_sync(0xffffffffu, ps1, 1);
        ps1 += __shfl_xor_sync(0xffffffffu, ps1, 2);
        l0 = l0 * al0 + ps0;
        l1 = l1 * al1 + ps1;

        // rescale O accumulators
        #pragma unroll
        for (int nt = 0; nt < 16; nt++) {
            o[nt][0] *= al0; o[nt][1] *= al0;
            o[nt][2] *= al1; o[nt][3] *= al1;
        }

        // ---- store P (tf32) to warp-private smem rows ----
        #pragma unroll
        for (int nt = 0; nt < 8; nt++) {
            int r = warp * 16 + gq;
            int c = nt * 8 + kq * 2;
            uint2 p0 = make_uint2(f2tf32(s[nt][0]), f2tf32(s[nt][1]));
            uint2 p1 = make_uint2(f2tf32(s[nt][2]), f2tf32(s[nt][3]));
            *reinterpret_cast<uint2*>(&Ps[r * PSTR + c]) = p0;
            *reinterpret_cast<uint2*>(&Ps[(r + 8) * PSTR + c]) = p1;
        }
        __syncwarp();

        // ---- O(16x128) += P(16x64) @ V(64x128) per warp ----
        #pragma unroll
        for (int ks = 0; ks < 8; ks++) {
            const int k0 = ks * 8;
            uint32_t a[4];
            a[0] = Ps[(warp * 16 + gq) * PSTR + k0 + kq];
            a[1] = Ps[(warp * 16 + gq + 8) * PSTR + k0 + kq];
            a[2] = Ps[(warp * 16 + gq) * PSTR + k0 + kq + 4];
            a[3] = Ps[(warp * 16 + gq + 8) * PSTR + k0 + kq + 4];
            #pragma unroll
            for (int nt = 0; nt < 16; nt++) {
                uint32_t b0 = Vs[(k0 + kq) * VSTR + nt * 8 + gq];
                uint32_t b1 = Vs[(k0 + kq + 4) * VSTR + nt * 8 + gq];
                mma_tf32(o[nt], a, b0, b1);
            }
        }
    }

    // ---- epilogue: normalize and write [s, h*dh] ----
    float il0 = 1.f / l0, il1 = 1.f / l1;
    #pragma unroll
    for (int nt = 0; nt < 16; nt++) {
        int r = qb * FM + warp * 16 + gq;
        int c = h * DH + nt * 8 + kq * 2;
        float2 r0 = make_float2(o[nt][0] * il0, o[nt][1] * il0);
        float2 r1 = make_float2(o[nt][2] * il1, o[nt][3] * il1);
        *reinterpret_cast<float2*>(&out[(size_t)r * DMODEL + c]) = r0;
        *reinterpret_cast<float2*>(&out[(size_t)(r + 8) * DMODEL + c]) = r1;
    }
}

// ---------------------------------------------------------------------------
// kernel_launch
// ---------------------------------------------------------------------------
extern "C" void kernel_launch(void* const* d_in, const int* in_sizes, int n_in,
                              void* d_out, int out_size)
{
    (void)in_sizes; (void)n_in; (void)out_size;
    const float* x         = (const float*)d_in[0];
    const float* Wqkv      = (const float*)d_in[1];
    const float* Wqkv_bias = (const float*)d_in[2];
    const float* out_w     = (const float*)d_in[3];
    const float* out_b     = (const float*)d_in[4];
    const float* attn_bias = (const float*)d_in[5];
    float* out = (float*)d_out;

    float* qkv  = nullptr;
    float* attn = nullptr;
    cudaGetSymbolAddress((void**)&qkv,  g_qkv);
    cudaGetSymbolAddress((void**)&attn, g_attn);

    // 1) QKV projection: [2048,2048] @ [2048,6144] + bias
    gemm_tf32<<<dim3(QKV_N / GBN, SEQ / GBM), 256>>>(
        x, Wqkv, Wqkv_bias, qkv, SEQ, QKV_N, DMODEL);

    // 2) Flash attention (tf32 MMA, causal + per-head key bias)
    cudaFuncSetAttribute(flash_tf32,
                         cudaFuncAttributeMaxDynamicSharedMemorySize, FLASH_SMEM);
    flash_tf32<<<dim3(SEQ / FM, NH), 256, FLASH_SMEM>>>(qkv, attn_bias, attn);

    // 3) Output projection: [2048,2048] @ [2048,2048] + bias
    gemm_tf32<<<dim3(DMODEL / GBN, SEQ / GBM), 256>>>(
        attn, out_w, out_b, out, SEQ, DMODEL, DMODEL);
}

// round 5
// speedup vs baseline: 8.5591x; 1.5751x over previous
#include <cuda_runtime.h>
#include <cuda_fp16.h>
#include <math.h>
#include <stdint.h>

#define SEQ    2048
#define DMODEL 2048
#define NH     16
#define DH     128
#define QKV_N  6144

// ---------------------------------------------------------------------------
// Scratch (__device__ globals; allocation-free rule)
// ---------------------------------------------------------------------------
__device__ __align__(16) __half g_xh[SEQ * DMODEL];
__device__ __align__(16) __half g_wqkvT[(size_t)QKV_N * DMODEL];   // [N][K]
__device__ __align__(16) __half g_woutT[(size_t)DMODEL * DMODEL];  // [N][K]
__device__ __align__(16) __half g_qkv[(size_t)SEQ * QKV_N];
__device__ __align__(16) __half g_attn[SEQ * DMODEL];

// ---------------------------------------------------------------------------
// PTX helpers
// ---------------------------------------------------------------------------
__device__ __forceinline__ uint32_t smem_u32(const void* p) {
    uint32_t a;
    asm("{ .reg .u64 t; cvta.to.shared.u64 t, %1; cvt.u32.u64 %0, t; }"
        : "=r"(a) : "l"(p));
    return a;
}
__device__ __forceinline__ void ldmx4(uint32_t r[4], uint32_t addr) {
    asm volatile("ldmatrix.sync.aligned.m8n8.x4.shared.b16 {%0,%1,%2,%3}, [%4];"
                 : "=r"(r[0]), "=r"(r[1]), "=r"(r[2]), "=r"(r[3]) : "r"(addr));
}
__device__ __forceinline__ void ldmx4t(uint32_t r[4], uint32_t addr) {
    asm volatile("ldmatrix.sync.aligned.m8n8.x4.trans.shared.b16 {%0,%1,%2,%3}, [%4];"
                 : "=r"(r[0]), "=r"(r[1]), "=r"(r[2]), "=r"(r[3]) : "r"(addr));
}
__device__ __forceinline__ void mma_f16(float c[4], const uint32_t a[4],
                                        uint32_t b0, uint32_t b1) {
    asm volatile(
        "mma.sync.aligned.m16n8k16.row.col.f32.f16.f16.f32 "
        "{%0,%1,%2,%3}, {%4,%5,%6,%7}, {%8,%9}, {%0,%1,%2,%3};"
        : "+f"(c[0]), "+f"(c[1]), "+f"(c[2]), "+f"(c[3])
        : "r"(a[0]), "r"(a[1]), "r"(a[2]), "r"(a[3]), "r"(b0), "r"(b1));
}
__device__ __forceinline__ void cp16(uint32_t dst, const void* src) {
    asm volatile("cp.async.cg.shared.global [%0], [%1], 16;" :: "r"(dst), "l"(src));
}
#define CP_COMMIT() asm volatile("cp.async.commit_group;" ::: "memory")
#define CP_WAIT1()  asm volatile("cp.async.wait_group 1;" ::: "memory")
#define CP_WAIT0()  asm volatile("cp.async.wait_group 0;" ::: "memory")

__device__ __forceinline__ uint32_t packh2(float a, float b) {
    __half2 h = __floats2half2_rn(a, b);
    return *reinterpret_cast<uint32_t*>(&h);
}

// ---------------------------------------------------------------------------
// Prepass: fp32 -> fp16 copy; fp32 [R][C] -> fp16 [C][R]
// ---------------------------------------------------------------------------
__global__ void cvt_h(const float* __restrict__ src, __half* __restrict__ dst) {
    int i = (blockIdx.x * 256 + threadIdx.x) * 4;
    float4 v = *reinterpret_cast<const float4*>(src + i);
    uint2 o;
    o.x = packh2(v.x, v.y);
    o.y = packh2(v.z, v.w);
    *reinterpret_cast<uint2*>(dst + i) = o;
}

__global__ void transpose_h(const float* __restrict__ src, __half* __restrict__ dst,
                            int R, int C) {
    __shared__ float t[32][33];
    int x = blockIdx.x * 32 + threadIdx.x;
    int y = blockIdx.y * 32 + threadIdx.y;
    #pragma unroll
    for (int j = 0; j < 32; j += 8)
        t[threadIdx.y + j][threadIdx.x] = src[(size_t)(y + j) * C + x];
    __syncthreads();
    int x2 = blockIdx.y * 32 + threadIdx.x;
    int y2 = blockIdx.x * 32 + threadIdx.y;
    #pragma unroll
    for (int j = 0; j < 32; j += 8)
        dst[(size_t)(y2 + j) * R + x2] = __float2half_rn(t[threadIdx.x][threadIdx.y + j]);
}

// ---------------------------------------------------------------------------
// fp16 tensor GEMM: C[M,N] = A[M,K] @ Bt[N,K]^T + bias
// 128x128 CTA tile, BK=64, 8 warps (4m x 2n), warp tile 32x64.
// cp.async double-buffered; ldmatrix fragments; 144B row pitch (conflict-free).
// ---------------------------------------------------------------------------
#define BKH 64
#define APITCH 72                       // halfs per row (144 bytes)
#define ATILE_B (128 * APITCH * 2)      // 18432 bytes per operand tile
#define STG_B (2 * ATILE_B)             // 36864 bytes per stage

__global__ __launch_bounds__(256, 2) void gemm_h(
    const __half* __restrict__ A, const __half* __restrict__ Bt,
    const float* __restrict__ bias, __half* __restrict__ Ch,
    float* __restrict__ Cf, int M, int N, int K)
{
    extern __shared__ char sh[];
    const uint32_t sbase = smem_u32(sh);

    const int tid  = threadIdx.x;
    const int warp = tid >> 5;
    const int lane = tid & 31;
    const int gq   = lane >> 2;
    const int kq   = lane & 3;
    const int wm   = warp >> 1;
    const int wn   = warp & 1;
    const int row0 = blockIdx.y * 128;
    const int col0 = blockIdx.x * 128;
    const int ntiles = K / BKH;

    const __half* gA = A  + (size_t)row0 * K;
    const __half* gB = Bt + (size_t)col0 * K;
    const int lr = tid >> 1;            // smem row 0..127 (2 threads/row)
    const int lb = (tid & 1) * 64;      // byte offset within 128B row: 0 or 64

    // fragment lane addressing (byte offsets)
    const uint32_t aOff = (uint32_t)((wm * 32 + (lane & 15)) * 144 + (lane >> 4) * 16);
    const int bRow = (lane & 7) + ((lane >> 4) & 1) * 8;
    const uint32_t bOff = (uint32_t)((wn * 64 + bRow) * 144 + ((lane >> 3) & 1) * 16);

    float acc[2][8][4];
    #pragma unroll
    for (int mt = 0; mt < 2; mt++)
        #pragma unroll
        for (int nt = 0; nt < 8; nt++)
            #pragma unroll
            for (int i = 0; i < 4; i++) acc[mt][nt][i] = 0.f;

    // ---- tile load (cp.async): 4 A chunks + 4 B chunks per thread (full 32KB)
    #define LOAD_TILE(t, s) do {                                                \
        uint32_t base_ = sbase + (uint32_t)(s) * STG_B;                         \
        const __half* a_  = gA + (size_t)lr * K + (t) * BKH + (lb >> 1);        \
        const __half* bb_ = gB + (size_t)lr * K + (t) * BKH + (lb >> 1);        \
        uint32_t da_ = base_ + (uint32_t)(lr * 144 + lb);                       \
        cp16(da_,      a_);      cp16(da_ + 16, a_ + 8);                        \
        cp16(da_ + 32, a_ + 16); cp16(da_ + 48, a_ + 24);                       \
        uint32_t db_ = da_ + ATILE_B;                                           \
        cp16(db_,      bb_);      cp16(db_ + 16, bb_ + 8);                      \
        cp16(db_ + 32, bb_ + 16); cp16(db_ + 48, bb_ + 24);                     \
        CP_COMMIT();                                                            \
    } while (0)

    #define COMPUTE(s) do {                                                     \
        uint32_t ab_ = sbase + (uint32_t)(s) * STG_B + aOff;                    \
        uint32_t bb2_ = sbase + (uint32_t)(s) * STG_B + ATILE_B + bOff;         \
        _Pragma("unroll")                                                       \
        for (int ks = 0; ks < 4; ks++) {                                        \
            uint32_t af0[4], af1[4];                                            \
            ldmx4(af0, ab_ + ks * 32);                                          \
            ldmx4(af1, ab_ + 16 * 144 + ks * 32);                               \
            _Pragma("unroll")                                                   \
            for (int p = 0; p < 4; p++) {                                       \
                uint32_t bf[4];                                                 \
                ldmx4(bf, bb2_ + p * (16 * 144) + ks * 32);                     \
                mma_f16(acc[0][2 * p],     af0, bf[0], bf[1]);                  \
                mma_f16(acc[0][2 * p + 1], af0, bf[2], bf[3]);                  \
                mma_f16(acc[1][2 * p],     af1, bf[0], bf[1]);                  \
                mma_f16(acc[1][2 * p + 1], af1, bf[2], bf[3]);                  \
            }                                                                   \
        }                                                                       \
    } while (0)

    LOAD_TILE(0, 0);
    for (int t = 1; t < ntiles; t++) {
        LOAD_TILE(t, t & 1);
        CP_WAIT1();
        __syncthreads();
        COMPUTE((t - 1) & 1);
        __syncthreads();
    }
    CP_WAIT0();
    __syncthreads();
    COMPUTE((ntiles - 1) & 1);

    // ---- epilogue ----
    #pragma unroll
    for (int mt = 0; mt < 2; mt++) {
        int r = row0 + wm * 32 + mt * 16 + gq;
        #pragma unroll
        for (int nt = 0; nt < 8; nt++) {
            int c = col0 + wn * 64 + nt * 8 + kq * 2;
            float b0 = bias[c], b1 = bias[c + 1];
            float v0 = acc[mt][nt][0] + b0, v1 = acc[mt][nt][1] + b1;
            float v2 = acc[mt][nt][2] + b0, v3 = acc[mt][nt][3] + b1;
            if (Ch) {
                *reinterpret_cast<uint32_t*>(&Ch[(size_t)r * N + c]) = packh2(v0, v1);
                *reinterpret_cast<uint32_t*>(&Ch[(size_t)(r + 8) * N + c]) = packh2(v2, v3);
            } else {
                *reinterpret_cast<float2*>(&Cf[(size_t)r * N + c]) = make_float2(v0, v1);
                *reinterpret_cast<float2*>(&Cf[(size_t)(r + 8) * N + c]) = make_float2(v2, v3);
            }
        }
    }
}

// ---------------------------------------------------------------------------
// Flash attention, fp16 MMA (causal + per-head additive key bias).
// BM=128 q-rows, BN=64 keys, DH=128. 8 warps, each owns 16 q-rows.
// P stays in registers (S accum fragment == PV A fragment).
// Smem pitch 136 halfs (272B) -> conflict-free ldmatrix.
// ---------------------------------------------------------------------------
#define FPITCH 136
#define QS_H (128 * FPITCH)
#define KS_H (64 * FPITCH)
#define VS_H (64 * FPITCH)
#define FLASH_SMEM ((QS_H + KS_H + VS_H) * 2)

__global__ __launch_bounds__(256, 2) void flash_h(
    const __half* __restrict__ qkv, const float* __restrict__ attn_bias,
    __half* __restrict__ out)
{
    extern __shared__ __half fsm[];
    __half* Qs = fsm;
    __half* Ks = Qs + QS_H;
    __half* Vs = Ks + KS_H;

    const int qb   = (gridDim.x - 1) - blockIdx.x;  // heavy blocks first
    const int h    = blockIdx.y;
    const int tid  = threadIdx.x;
    const int warp = tid >> 5;
    const int lane = tid & 31;
    const int gq   = lane >> 2;
    const int kq   = lane & 3;

    const float scale = 0.08838834764831845f;  // 1/sqrt(128)
    const float* bh = attn_bias + (size_t)h * SEQ;

    const uint32_t qsb = smem_u32(Qs);
    const uint32_t ksb = smem_u32(Ks);
    const uint32_t vsb = smem_u32(Vs);

    // fragment lane addressing (byte offsets)
    const uint32_t qOff = qsb + (uint32_t)((warp * 16 + (lane & 15)) * 272 + (lane >> 4) * 16);
    const int kRow = (lane & 7) + ((lane >> 4) & 1) * 8;
    const uint32_t kOff = ksb + (uint32_t)(kRow * 272 + ((lane >> 3) & 1) * 16);
    const int vRow = (lane & 7) + ((lane >> 3) & 1) * 8;
    const uint32_t vOff = vsb + (uint32_t)(vRow * 272 + ((lane >> 4) & 1) * 16);

    // ---- load Q tile (128 x 128 halfs) ----
    #pragma unroll
    for (int i = 0; i < 8; i++) {
        int idx = tid + i * 256;           // 16B chunk id
        int r = idx >> 4, c = idx & 15;
        uint4 v = *reinterpret_cast<const uint4*>(
            &qkv[(size_t)(qb * 128 + r) * QKV_N + h * DH + c * 8]);
        *reinterpret_cast<uint4*>(&Qs[r * FPITCH + c * 8]) = v;
    }

    float o[16][4];
    #pragma unroll
    for (int nt = 0; nt < 16; nt++)
        #pragma unroll
        for (int i = 0; i < 4; i++) o[nt][i] = 0.f;
    float m0 = -1e30f, m1 = -1e30f, l0 = 0.f, l1 = 0.f;

    const int qrow0 = qb * 128 + warp * 16 + gq;
    const int nkb = 2 * qb + 2;

    for (int kb = 0; kb < nkb; kb++) {
        __syncthreads();
        // load K, V blocks (64 x 128 halfs each)
        #pragma unroll
        for (int i = 0; i < 4; i++) {
            int idx = tid + i * 256;
            int r = idx >> 4, c = idx & 15;
            const __half* kp = &qkv[(size_t)(kb * 64 + r) * QKV_N + DMODEL + h * DH + c * 8];
            *reinterpret_cast<uint4*>(&Ks[r * FPITCH + c * 8]) =
                *reinterpret_cast<const uint4*>(kp);
            *reinterpret_cast<uint4*>(&Vs[r * FPITCH + c * 8]) =
                *reinterpret_cast<const uint4*>(kp + DMODEL);
        }
        __syncthreads();

        // ---- S(16x64) = Q @ K^T ----
        float s[8][4];
        #pragma unroll
        for (int nt = 0; nt < 8; nt++)
            #pragma unroll
            for (int i = 0; i < 4; i++) s[nt][i] = 0.f;

        #pragma unroll
        for (int ks = 0; ks < 8; ks++) {
            uint32_t aq[4];
            ldmx4(aq, qOff + ks * 32);
            #pragma unroll
            for (int p = 0; p < 4; p++) {
                uint32_t bf[4];
                ldmx4(bf, kOff + p * (16 * 272) + ks * 32);
                mma_f16(s[2 * p],     aq, bf[0], bf[1]);
                mma_f16(s[2 * p + 1], aq, bf[2], bf[3]);
            }
        }

        // ---- bias + scale + causal mask ----
        const bool diag = (kb >= 2 * qb);
        #pragma unroll
        for (int nt = 0; nt < 8; nt++) {
            int j = nt * 8 + kq * 2;
            float b0v = bh[kb * 64 + j], b1v = bh[kb * 64 + j + 1];
            s[nt][0] = s[nt][0] * scale + b0v;
            s[nt][1] = s[nt][1] * scale + b1v;
            s[nt][2] = s[nt][2] * scale + b0v;
            s[nt][3] = s[nt][3] * scale + b1v;
            if (diag) {
                int jg = kb * 64 + j;
                if (jg     > qrow0)     s[nt][0] = -1e30f;
                if (jg + 1 > qrow0)     s[nt][1] = -1e30f;
                if (jg     > qrow0 + 8) s[nt][2] = -1e30f;
                if (jg + 1 > qrow0 + 8) s[nt][3] = -1e30f;
            }
        }

        // ---- online softmax ----
        float mx0 = -1e30f, mx1 = -1e30f;
        #pragma unroll
        for (int nt = 0; nt < 8; nt++) {
            mx0 = fmaxf(mx0, fmaxf(s[nt][0], s[nt][1]));
            mx1 = fmaxf(mx1, fmaxf(s[nt][2], s[nt][3]));
        }
        mx0 = fmaxf(mx0, __shfl_xor_sync(0xffffffffu, mx0, 1));
        mx0 = fmaxf(mx0, __shfl_xor_sync(0xffffffffu, mx0, 2));
        mx1 = fmaxf(mx1, __shfl_xor_sync(0xffffffffu, mx1, 1));
        mx1 = fmaxf(mx1, __shfl_xor_sync(0xffffffffu, mx1, 2));

        float mn0 = fmaxf(m0, mx0), mn1 = fmaxf(m1, mx1);
        float al0 = __expf(m0 - mn0), al1 = __expf(m1 - mn1);
        m0 = mn0; m1 = mn1;

        float ps0 = 0.f, ps1 = 0.f;
        #pragma unroll
        for (int nt = 0; nt < 8; nt++) {
            s[nt][0] = __expf(s[nt][0] - mn0);
            s[nt][1] = __expf(s[nt][1] - mn0);
            s[nt][2] = __expf(s[nt][2] - mn1);
            s[nt][3] = __expf(s[nt][3] - mn1);
            ps0 += s[nt][0] + s[nt][1];
            ps1 += s[nt][2] + s[nt][3];
        }
        ps0 += __shfl_xor_sync(0xffffffffu, ps0, 1);
        ps0 += __shfl_xor_sync(0xffffffffu, ps0, 2);
        ps1 += __shfl_xor_sync(0xffffffffu, ps1, 1);
        ps1 += __shfl_xor_sync(0xffffffffu, ps1, 2);
        l0 = l0 * al0 + ps0;
        l1 = l1 * al1 + ps1;

        #pragma unroll
        for (int nt = 0; nt < 16; nt++) {
            o[nt][0] *= al0; o[nt][1] *= al0;
            o[nt][2] *= al1; o[nt][3] *= al1;
        }

        // ---- O(16x128) += P(16x64) @ V : P straight from registers ----
        #pragma unroll
        for (int ks = 0; ks < 4; ks++) {
            uint32_t ap[4];
            ap[0] = packh2(s[2 * ks][0],     s[2 * ks][1]);
            ap[1] = packh2(s[2 * ks][2],     s[2 * ks][3]);
            ap[2] = packh2(s[2 * ks + 1][0], s[2 * ks + 1][1]);
            ap[3] = packh2(s[2 * ks + 1][2], s[2 * ks + 1][3]);
            #pragma unroll
            for (int p = 0; p < 8; p++) {
                uint32_t bf[4];
                ldmx4t(bf, vOff + ks * (16 * 272) + p * 32);
                mma_f16(o[2 * p],     ap, bf[0], bf[1]);
                mma_f16(o[2 * p + 1], ap, bf[2], bf[3]);
            }
        }
    }

    // ---- epilogue: normalize, write fp16 [s, h*dh] ----
    float il0 = 1.f / l0, il1 = 1.f / l1;
    int r = qb * 128 + warp * 16 + gq;
    #pragma unroll
    for (int nt = 0; nt < 16; nt++) {
        int c = h * DH + nt * 8 + kq * 2;
        *reinterpret_cast<uint32_t*>(&out[(size_t)r * DMODEL + c]) =
            packh2(o[nt][0] * il0, o[nt][1] * il0);
        *reinterpret_cast<uint32_t*>(&out[(size_t)(r + 8) * DMODEL + c]) =
            packh2(o[nt][2] * il1, o[nt][3] * il1);
    }
}

// ---------------------------------------------------------------------------
// kernel_launch
// ---------------------------------------------------------------------------
extern "C" void kernel_launch(void* const* d_in, const int* in_sizes, int n_in,
                              void* d_out, int out_size)
{
    (void)in_sizes; (void)n_in; (void)out_size;
    const float* x         = (const float*)d_in[0];
    const float* Wqkv      = (const float*)d_in[1];
    const float* Wqkv_bias = (const float*)d_in[2];
    const float* out_w     = (const float*)d_in[3];
    const float* out_b     = (const float*)d_in[4];
    const float* attn_bias = (const float*)d_in[5];
    float* out = (float*)d_out;

    __half *xh, *wqkvT, *woutT, *qkv, *attn;
    cudaGetSymbolAddress((void**)&xh,    g_xh);
    cudaGetSymbolAddress((void**)&wqkvT, g_wqkvT);
    cudaGetSymbolAddress((void**)&woutT, g_woutT);
    cudaGetSymbolAddress((void**)&qkv,   g_qkv);
    cudaGetSymbolAddress((void**)&attn,  g_attn);

    cudaFuncSetAttribute(gemm_h, cudaFuncAttributeMaxDynamicSharedMemorySize,
                         2 * STG_B);
    cudaFuncSetAttribute(flash_h, cudaFuncAttributeMaxDynamicSharedMemorySize,
                         FLASH_SMEM);

    // 0) prepass: fp16 conversions / weight transposes
    cvt_h<<<SEQ * DMODEL / 1024, 256>>>(x, xh);
    transpose_h<<<dim3(QKV_N / 32, DMODEL / 32), dim3(32, 8)>>>(Wqkv, wqkvT, DMODEL, QKV_N);
    transpose_h<<<dim3(DMODEL / 32, DMODEL / 32), dim3(32, 8)>>>(out_w, woutT, DMODEL, DMODEL);

    // 1) QKV projection -> fp16 qkv
    gemm_h<<<dim3(QKV_N / 128, SEQ / 128), 256, 2 * STG_B>>>(
        xh, wqkvT, Wqkv_bias, qkv, nullptr, SEQ, QKV_N, DMODEL);

    // 2) Flash attention -> fp16 attn
    flash_h<<<dim3(SEQ / 128, NH), 256, FLASH_SMEM>>>(qkv, attn_bias, attn);

    // 3) Output projection -> fp32 out
    gemm_h<<<dim3(DMODEL / 128, SEQ / 128), 256, 2 * STG_B>>>(
        attn, woutT, out_b, nullptr, out, SEQ, DMODEL, DMODEL);
}

// round 6
// speedup vs baseline: 8.8022x; 1.0284x over previous
#include <cuda_runtime.h>
#include <cuda_fp16.h>
#include <math.h>
#include <stdint.h>

#define SEQ    2048
#define DMODEL 2048
#define NH     16
#define DH     128
#define QKV_N  6144

// ---------------------------------------------------------------------------
// Scratch (__device__ globals; allocation-free rule)
// ---------------------------------------------------------------------------
__device__ __align__(16) __half g_xh[SEQ * DMODEL];
__device__ __align__(16) __half g_wqkvT[(size_t)QKV_N * DMODEL];   // [N][K]
__device__ __align__(16) __half g_woutT[(size_t)DMODEL * DMODEL];  // [N][K]
__device__ __align__(16) __half g_qkv[(size_t)SEQ * QKV_N];
__device__ __align__(16) __half g_attn[SEQ * DMODEL];

// ---------------------------------------------------------------------------
// PTX helpers
// ---------------------------------------------------------------------------
__device__ __forceinline__ uint32_t smem_u32(const void* p) {
    uint32_t a;
    asm("{ .reg .u64 t; cvta.to.shared.u64 t, %1; cvt.u32.u64 %0, t; }"
        : "=r"(a) : "l"(p));
    return a;
}
__device__ __forceinline__ void ldmx4(uint32_t r[4], uint32_t addr) {
    asm volatile("ldmatrix.sync.aligned.m8n8.x4.shared.b16 {%0,%1,%2,%3}, [%4];"
                 : "=r"(r[0]), "=r"(r[1]), "=r"(r[2]), "=r"(r[3]) : "r"(addr));
}
__device__ __forceinline__ void ldmx4t(uint32_t r[4], uint32_t addr) {
    asm volatile("ldmatrix.sync.aligned.m8n8.x4.trans.shared.b16 {%0,%1,%2,%3}, [%4];"
                 : "=r"(r[0]), "=r"(r[1]), "=r"(r[2]), "=r"(r[3]) : "r"(addr));
}
__device__ __forceinline__ void mma_f16(float c[4], const uint32_t a[4],
                                        uint32_t b0, uint32_t b1) {
    asm volatile(
        "mma.sync.aligned.m16n8k16.row.col.f32.f16.f16.f32 "
        "{%0,%1,%2,%3}, {%4,%5,%6,%7}, {%8,%9}, {%0,%1,%2,%3};"
        : "+f"(c[0]), "+f"(c[1]), "+f"(c[2]), "+f"(c[3])
        : "r"(a[0]), "r"(a[1]), "r"(a[2]), "r"(a[3]), "r"(b0), "r"(b1));
}
__device__ __forceinline__ void cp16(uint32_t dst, const void* src) {
    asm volatile("cp.async.cg.shared.global [%0], [%1], 16;" :: "r"(dst), "l"(src));
}
#define CP_COMMIT() asm volatile("cp.async.commit_group;" ::: "memory")
#define CP_WAIT0()  asm volatile("cp.async.wait_group 0;" ::: "memory")

__device__ __forceinline__ uint32_t packh2(float a, float b) {
    __half2 h = __floats2half2_rn(a, b);
    return *reinterpret_cast<uint32_t*>(&h);
}

// ---------------------------------------------------------------------------
// Prepass: fp32 -> fp16 copy; fp32 [R][C] -> fp16 [C][R]
// ---------------------------------------------------------------------------
__global__ void cvt_h(const float* __restrict__ src, __half* __restrict__ dst) {
    int i = (blockIdx.x * 256 + threadIdx.x) * 4;
    float4 v = *reinterpret_cast<const float4*>(src + i);
    uint2 o;
    o.x = packh2(v.x, v.y);
    o.y = packh2(v.z, v.w);
    *reinterpret_cast<uint2*>(dst + i) = o;
}

__global__ void transpose_h(const float* __restrict__ src, __half* __restrict__ dst,
                            int R, int C) {
    __shared__ float t[32][33];
    int x = blockIdx.x * 32 + threadIdx.x;
    int y = blockIdx.y * 32 + threadIdx.y;
    #pragma unroll
    for (int j = 0; j < 32; j += 8)
        t[threadIdx.y + j][threadIdx.x] = src[(size_t)(y + j) * C + x];
    __syncthreads();
    int x2 = blockIdx.y * 32 + threadIdx.x;
    int y2 = blockIdx.x * 32 + threadIdx.y;
    #pragma unroll
    for (int j = 0; j < 32; j += 8)
        dst[(size_t)(y2 + j) * R + x2] = __float2half_rn(t[threadIdx.x][threadIdx.y + j]);
}

// ---------------------------------------------------------------------------
// fp16 tensor GEMM: C[M,N] = A[M,K] @ Bt[N,K]^T + bias
// 128x128 CTA tile, BK=64, 8 warps (4m x 2n), warp tile 32x64.
// 2-stage cp.async pipeline, ONE __syncthreads per tile (load-behind-barrier).
// ---------------------------------------------------------------------------
#define BKH 64
#define APITCH 72                       // halfs per row (144 bytes)
#define ATILE_B (128 * APITCH * 2)      // 18432 bytes per operand tile
#define STG_B (2 * ATILE_B)             // 36864 bytes per stage

__global__ __launch_bounds__(256, 2) void gemm_h(
    const __half* __restrict__ A, const __half* __restrict__ Bt,
    const float* __restrict__ bias, __half* __restrict__ Ch,
    float* __restrict__ Cf, int M, int N, int K)
{
    extern __shared__ char sh[];
    const uint32_t sbase = smem_u32(sh);

    const int tid  = threadIdx.x;
    const int warp = tid >> 5;
    const int lane = tid & 31;
    const int gq   = lane >> 2;
    const int kq   = lane & 3;
    const int wm   = warp >> 1;
    const int wn   = warp & 1;
    const int row0 = blockIdx.y * 128;
    const int col0 = blockIdx.x * 128;
    const int ntiles = K / BKH;

    const __half* gA = A  + (size_t)row0 * K;
    const __half* gB = Bt + (size_t)col0 * K;
    const int lr = tid >> 1;            // smem row 0..127 (2 threads/row)
    const int lb = (tid & 1) * 64;      // byte offset within 128B row: 0 or 64

    // fragment lane addressing (byte offsets)
    const uint32_t aOff = (uint32_t)((wm * 32 + (lane & 15)) * 144 + (lane >> 4) * 16);
    const int bRow = (lane & 7) + ((lane >> 4) & 1) * 8;
    const uint32_t bOff = (uint32_t)((wn * 64 + bRow) * 144 + ((lane >> 3) & 1) * 16);

    float acc[2][8][4];
    #pragma unroll
    for (int mt = 0; mt < 2; mt++)
        #pragma unroll
        for (int nt = 0; nt < 8; nt++)
            #pragma unroll
            for (int i = 0; i < 4; i++) acc[mt][nt][i] = 0.f;

    // ---- tile load (cp.async): 4 A chunks + 4 B chunks per thread (32KB) ----
    #define LOAD_TILE(t, s) do {                                                \
        uint32_t base_ = sbase + (uint32_t)(s) * STG_B;                         \
        const __half* a_  = gA + (size_t)lr * K + (t) * BKH + (lb >> 1);        \
        const __half* bb_ = gB + (size_t)lr * K + (t) * BKH + (lb >> 1);        \
        uint32_t da_ = base_ + (uint32_t)(lr * 144 + lb);                       \
        cp16(da_,      a_);      cp16(da_ + 16, a_ + 8);                        \
        cp16(da_ + 32, a_ + 16); cp16(da_ + 48, a_ + 24);                       \
        uint32_t db_ = da_ + ATILE_B;                                           \
        cp16(db_,      bb_);      cp16(db_ + 16, bb_ + 8);                      \
        cp16(db_ + 32, bb_ + 16); cp16(db_ + 48, bb_ + 24);                     \
        CP_COMMIT();                                                            \
    } while (0)

    #define COMPUTE(s) do {                                                     \
        uint32_t ab_ = sbase + (uint32_t)(s) * STG_B + aOff;                    \
        uint32_t bb2_ = sbase + (uint32_t)(s) * STG_B + ATILE_B + bOff;         \
        _Pragma("unroll")                                                       \
        for (int ks = 0; ks < 4; ks++) {                                        \
            uint32_t af0[4], af1[4];                                            \
            ldmx4(af0, ab_ + ks * 32);                                          \
            ldmx4(af1, ab_ + 16 * 144 + ks * 32);                               \
            _Pragma("unroll")                                                   \
            for (int p = 0; p < 4; p++) {                                       \
                uint32_t bf[4];                                                 \
                ldmx4(bf, bb2_ + p * (16 * 144) + ks * 32);                     \
                mma_f16(acc[0][2 * p],     af0, bf[0], bf[1]);                  \
                mma_f16(acc[0][2 * p + 1], af0, bf[2], bf[3]);                  \
                mma_f16(acc[1][2 * p],     af1, bf[0], bf[1]);                  \
                mma_f16(acc[1][2 * p + 1], af1, bf[2], bf[3]);                  \
            }                                                                   \
        }                                                                       \
    } while (0)

    LOAD_TILE(0, 0);
    for (int t = 0; t < ntiles; t++) {
        CP_WAIT0();
        __syncthreads();
        if (t + 1 < ntiles) LOAD_TILE(t + 1, (t + 1) & 1);
        COMPUTE(t & 1);
    }

    // ---- epilogue ----
    #pragma unroll
    for (int mt = 0; mt < 2; mt++) {
        int r = row0 + wm * 32 + mt * 16 + gq;
        #pragma unroll
        for (int nt = 0; nt < 8; nt++) {
            int c = col0 + wn * 64 + nt * 8 + kq * 2;
            float b0 = bias[c], b1 = bias[c + 1];
            float v0 = acc[mt][nt][0] + b0, v1 = acc[mt][nt][1] + b1;
            float v2 = acc[mt][nt][2] + b0, v3 = acc[mt][nt][3] + b1;
            if (Ch) {
                *reinterpret_cast<uint32_t*>(&Ch[(size_t)r * N + c]) = packh2(v0, v1);
                *reinterpret_cast<uint32_t*>(&Ch[(size_t)(r + 8) * N + c]) = packh2(v2, v3);
            } else {
                *reinterpret_cast<float2*>(&Cf[(size_t)r * N + c]) = make_float2(v0, v1);
                *reinterpret_cast<float2*>(&Cf[(size_t)(r + 8) * N + c]) = make_float2(v2, v3);
            }
        }
    }
}

// ---------------------------------------------------------------------------
// Flash attention, fp16 MMA (causal + per-head additive key bias).
// BM=128 q-rows, BN=64 keys, DH=128. 8 warps, each owns 16 q-rows.
// P stays in registers. 2-stage cp.async K/V ring, ONE __syncthreads per kb.
// Smem pitch 136 halfs (272B) -> conflict-free ldmatrix.
// ---------------------------------------------------------------------------
#define FPITCH 136
#define QTILE_B (128 * FPITCH * 2)      // 34816
#define KTILE_B (64 * FPITCH * 2)       // 17408
#define KVSTG_B (2 * KTILE_B)           // 34816 (K tile + V tile)
#define FLASH_SMEM (QTILE_B + 2 * KVSTG_B)

__global__ __launch_bounds__(256, 2) void flash_h(
    const __half* __restrict__ qkv, const float* __restrict__ attn_bias,
    __half* __restrict__ out)
{
    extern __shared__ char fsm[];
    const uint32_t qsb  = smem_u32(fsm);
    const uint32_t kvsb = qsb + QTILE_B;

    const int qb   = (gridDim.x - 1) - blockIdx.x;  // heavy blocks first
    const int h    = blockIdx.y;
    const int tid  = threadIdx.x;
    const int warp = tid >> 5;
    const int lane = tid & 31;
    const int gq   = lane >> 2;
    const int kq   = lane & 3;

    const float scale = 0.08838834764831845f;  // 1/sqrt(128)
    const float* bh = attn_bias + (size_t)h * SEQ;

    // fragment lane addressing (byte offsets, stage-relative for K/V)
    const uint32_t qOff = qsb + (uint32_t)((warp * 16 + (lane & 15)) * 272 + (lane >> 4) * 16);
    const int kRow = (lane & 7) + ((lane >> 4) & 1) * 8;
    const uint32_t kRel = (uint32_t)(kRow * 272 + ((lane >> 3) & 1) * 16);
    const int vRow = (lane & 7) + ((lane >> 3) & 1) * 8;
    const uint32_t vRel = (uint32_t)(vRow * 272 + ((lane >> 4) & 1) * 16) + KTILE_B;

    // ---- K/V block load (cp.async): 4 chunks K + 4 chunks V per thread ----
    #define LOADKV(kb_, s_) do {                                                \
        uint32_t kvb_ = kvsb + (uint32_t)(s_) * KVSTG_B;                        \
        _Pragma("unroll")                                                       \
        for (int i_ = 0; i_ < 4; i_++) {                                        \
            int idx_ = tid + i_ * 256;                                          \
            int r_ = idx_ >> 4, c_ = idx_ & 15;                                 \
            const __half* kp_ = &qkv[(size_t)((kb_) * 64 + r_) * QKV_N          \
                                     + DMODEL + h * DH + c_ * 8];               \
            uint32_t d_ = kvb_ + (uint32_t)(r_ * 272 + c_ * 16);                \
            cp16(d_, kp_);                                                      \
            cp16(d_ + KTILE_B, kp_ + DMODEL);                                   \
        }                                                                       \
        CP_COMMIT();                                                            \
    } while (0)

    // ---- prologue: Q tile (cp.async) + K/V block 0, one group ----
    #pragma unroll
    for (int i = 0; i < 8; i++) {
        int idx = tid + i * 256;           // 16B chunk id
        int r = idx >> 4, c = idx & 15;
        cp16(qsb + (uint32_t)(r * 272 + c * 16),
             &qkv[(size_t)(qb * 128 + r) * QKV_N + h * DH + c * 8]);
    }
    LOADKV(0, 0);

    float o[16][4];
    #pragma unroll
    for (int nt = 0; nt < 16; nt++)
        #pragma unroll
        for (int i = 0; i < 4; i++) o[nt][i] = 0.f;
    float m0 = -1e30f, m1 = -1e30f, l0 = 0.f, l1 = 0.f;

    const int qrow0 = qb * 128 + warp * 16 + gq;
    const int nkb = 2 * qb + 2;

    for (int kb = 0; kb < nkb; kb++) {
        CP_WAIT0();
        __syncthreads();
        if (kb + 1 < nkb) LOADKV(kb + 1, (kb + 1) & 1);

        const uint32_t stg = kvsb + (uint32_t)(kb & 1) * KVSTG_B;
        const uint32_t kOff = stg + kRel;
        const uint32_t vOff = stg + vRel;

        // ---- S(16x64) = Q @ K^T ----
        float s[8][4];
        #pragma unroll
        for (int nt = 0; nt < 8; nt++)
            #pragma unroll
            for (int i = 0; i < 4; i++) s[nt][i] = 0.f;

        #pragma unroll
        for (int ks = 0; ks < 8; ks++) {
            uint32_t aq[4];
            ldmx4(aq, qOff + ks * 32);
            #pragma unroll
            for (int p = 0; p < 4; p++) {
                uint32_t bf[4];
                ldmx4(bf, kOff + p * (16 * 272) + ks * 32);
                mma_f16(s[2 * p],     aq, bf[0], bf[1]);
                mma_f16(s[2 * p + 1], aq, bf[2], bf[3]);
            }
        }

        // ---- bias + scale + causal mask ----
        const bool diag = (kb >= 2 * qb);
        #pragma unroll
        for (int nt = 0; nt < 8; nt++) {
            int j = nt * 8 + kq * 2;
            float b0v = bh[kb * 64 + j], b1v = bh[kb * 64 + j + 1];
            s[nt][0] = s[nt][0] * scale + b0v;
            s[nt][1] = s[nt][1] * scale + b1v;
            s[nt][2] = s[nt][2] * scale + b0v;
            s[nt][3] = s[nt][3] * scale + b1v;
            if (diag) {
                int jg = kb * 64 + j;
                if (jg     > qrow0)     s[nt][0] = -1e30f;
                if (jg + 1 > qrow0)     s[nt][1] = -1e30f;
                if (jg     > qrow0 + 8) s[nt][2] = -1e30f;
                if (jg + 1 > qrow0 + 8) s[nt][3] = -1e30f;
            }
        }

        // ---- online softmax ----
        float mx0 = -1e30f, mx1 = -1e30f;
        #pragma unroll
        for (int nt = 0; nt < 8; nt++) {
            mx0 = fmaxf(mx0, fmaxf(s[nt][0], s[nt][1]));
            mx1 = fmaxf(mx1, fmaxf(s[nt][2], s[nt][3]));
        }
        mx0 = fmaxf(mx0, __shfl_xor_sync(0xffffffffu, mx0, 1));
        mx0 = fmaxf(mx0, __shfl_xor_sync(0xffffffffu, mx0, 2));
        mx1 = fmaxf(mx1, __shfl_xor_sync(0xffffffffu, mx1, 1));
        mx1 = fmaxf(mx1, __shfl_xor_sync(0xffffffffu, mx1, 2));

        float mn0 = fmaxf(m0, mx0), mn1 = fmaxf(m1, mx1);
        float al0 = __expf(m0 - mn0), al1 = __expf(m1 - mn1);
        m0 = mn0; m1 = mn1;

        float ps0 = 0.f, ps1 = 0.f;
        #pragma unroll
        for (int nt = 0; nt < 8; nt++) {
            s[nt][0] = __expf(s[nt][0] - mn0);
            s[nt][1] = __expf(s[nt][1] - mn0);
            s[nt][2] = __expf(s[nt][2] - mn1);
            s[nt][3] = __expf(s[nt][3] - mn1);
            ps0 += s[nt][0] + s[nt][1];
            ps1 += s[nt][2] + s[nt][3];
        }
        ps0 += __shfl_xor_sync(0xffffffffu, ps0, 1);
        ps0 += __shfl_xor_sync(0xffffffffu, ps0, 2);
        ps1 += __shfl_xor_sync(0xffffffffu, ps1, 1);
        ps1 += __shfl_xor_sync(0xffffffffu, ps1, 2);
        l0 = l0 * al0 + ps0;
        l1 = l1 * al1 + ps1;

        #pragma unroll
        for (int nt = 0; nt < 16; nt++) {
            o[nt][0] *= al0; o[nt][1] *= al0;
            o[nt][2] *= al1; o[nt][3] *= al1;
        }

        // ---- O(16x128) += P(16x64) @ V : P straight from registers ----
        #pragma unroll
        for (int ks = 0; ks < 4; ks++) {
            uint32_t ap[4];
            ap[0] = packh2(s[2 * ks][0],     s[2 * ks][1]);
            ap[1] = packh2(s[2 * ks][2],     s[2 * ks][3]);
            ap[2] = packh2(s[2 * ks + 1][0], s[2 * ks + 1][1]);
            ap[3] = packh2(s[2 * ks + 1][2], s[2 * ks + 1][3]);
            #pragma unroll
            for (int p = 0; p < 8; p++) {
                uint32_t bf[4];
                ldmx4t(bf, vOff + ks * (16 * 272) + p * 32);
                mma_f16(o[2 * p],     ap, bf[0], bf[1]);
                mma_f16(o[2 * p + 1], ap, bf[2], bf[3]);
            }
        }
    }

    // ---- epilogue: normalize, write fp16 [s, h*dh] ----
    float il0 = 1.f / l0, il1 = 1.f / l1;
    int r = qb * 128 + warp * 16 + gq;
    #pragma unroll
    for (int nt = 0; nt < 16; nt++) {
        int c = h * DH + nt * 8 + kq * 2;
        *reinterpret_cast<uint32_t*>(&out[(size_t)r * DMODEL + c]) =
            packh2(o[nt][0] * il0, o[nt][1] * il0);
        *reinterpret_cast<uint32_t*>(&out[(size_t)(r + 8) * DMODEL + c]) =
            packh2(o[nt][2] * il1, o[nt][3] * il1);
    }
}

// ---------------------------------------------------------------------------
// kernel_launch
// ---------------------------------------------------------------------------
extern "C" void kernel_launch(void* const* d_in, const int* in_sizes, int n_in,
                              void* d_out, int out_size)
{
    (void)in_sizes; (void)n_in; (void)out_size;
    const float* x         = (const float*)d_in[0];
    const float* Wqkv      = (const float*)d_in[1];
    const float* Wqkv_bias = (const float*)d_in[2];
    const float* out_w     = (const float*)d_in[3];
    const float* out_b     = (const float*)d_in[4];
    const float* attn_bias = (const float*)d_in[5];
    float* out = (float*)d_out;

    __half *xh, *wqkvT, *woutT, *qkv, *attn;
    cudaGetSymbolAddress((void**)&xh,    g_xh);
    cudaGetSymbolAddress((void**)&wqkvT, g_wqkvT);
    cudaGetSymbolAddress((void**)&woutT, g_woutT);
    cudaGetSymbolAddress((void**)&qkv,   g_qkv);
    cudaGetSymbolAddress((void**)&attn,  g_attn);

    cudaFuncSetAttribute(gemm_h, cudaFuncAttributeMaxDynamicSharedMemorySize,
                         2 * STG_B);
    cudaFuncSetAttribute(flash_h, cudaFuncAttributeMaxDynamicSharedMemorySize,
                         FLASH_SMEM);

    // 0) prepass: fp16 conversions / weight transposes
    cvt_h<<<SEQ * DMODEL / 1024, 256>>>(x, xh);
    transpose_h<<<dim3(QKV_N / 32, DMODEL / 32), dim3(32, 8)>>>(Wqkv, wqkvT, DMODEL, QKV_N);
    transpose_h<<<dim3(DMODEL / 32, DMODEL / 32), dim3(32, 8)>>>(out_w, woutT, DMODEL, DMODEL);

    // 1) QKV projection -> fp16 qkv
    gemm_h<<<dim3(QKV_N / 128, SEQ / 128), 256, 2 * STG_B>>>(
        xh, wqkvT, Wqkv_bias, qkv, nullptr, SEQ, QKV_N, DMODEL);

    // 2) Flash attention -> fp16 attn
    flash_h<<<dim3(SEQ / 128, NH), 256, FLASH_SMEM>>>(qkv, attn_bias, attn);

    // 3) Output projection -> fp32 out
    gemm_h<<<dim3(DMODEL / 128, SEQ / 128), 256, 2 * STG_B>>>(
        attn, woutT, out_b, nullptr, out, SEQ, DMODEL, DMODEL);
}

// round 7
// speedup vs baseline: 9.2902x; 1.0554x over previous
#include <cuda_runtime.h>
#include <cuda_fp16.h>
#include <math.h>
#include <stdint.h>

#define SEQ    2048
#define DMODEL 2048
#define NH     16
#define DH     128
#define QKV_N  6144

// ---------------------------------------------------------------------------
// Scratch (__device__ globals; allocation-free rule)
// ---------------------------------------------------------------------------
__device__ __align__(16) __half g_xh[SEQ * DMODEL];
__device__ __align__(16) __half g_wqkvh[(size_t)DMODEL * QKV_N];   // [K][N] fp16
__device__ __align__(16) __half g_wouth[(size_t)DMODEL * DMODEL];  // [K][N] fp16
__device__ __align__(16) __half g_qkv[(size_t)SEQ * QKV_N];
__device__ __align__(16) __half g_attn[SEQ * DMODEL];

// ---------------------------------------------------------------------------
// PTX helpers
// ---------------------------------------------------------------------------
__device__ __forceinline__ uint32_t smem_u32(const void* p) {
    uint32_t a;
    asm("{ .reg .u64 t; cvta.to.shared.u64 t, %1; cvt.u32.u64 %0, t; }"
        : "=r"(a) : "l"(p));
    return a;
}
__device__ __forceinline__ void ldmx4(uint32_t r[4], uint32_t addr) {
    asm volatile("ldmatrix.sync.aligned.m8n8.x4.shared.b16 {%0,%1,%2,%3}, [%4];"
                 : "=r"(r[0]), "=r"(r[1]), "=r"(r[2]), "=r"(r[3]) : "r"(addr));
}
__device__ __forceinline__ void ldmx4t(uint32_t r[4], uint32_t addr) {
    asm volatile("ldmatrix.sync.aligned.m8n8.x4.trans.shared.b16 {%0,%1,%2,%3}, [%4];"
                 : "=r"(r[0]), "=r"(r[1]), "=r"(r[2]), "=r"(r[3]) : "r"(addr));
}
__device__ __forceinline__ void mma_f16(float c[4], const uint32_t a[4],
                                        uint32_t b0, uint32_t b1) {
    asm volatile(
        "mma.sync.aligned.m16n8k16.row.col.f32.f16.f16.f32 "
        "{%0,%1,%2,%3}, {%4,%5,%6,%7}, {%8,%9}, {%0,%1,%2,%3};"
        : "+f"(c[0]), "+f"(c[1]), "+f"(c[2]), "+f"(c[3])
        : "r"(a[0]), "r"(a[1]), "r"(a[2]), "r"(a[3]), "r"(b0), "r"(b1));
}
__device__ __forceinline__ void cp16(uint32_t dst, const void* src) {
    asm volatile("cp.async.cg.shared.global [%0], [%1], 16;" :: "r"(dst), "l"(src));
}
#define CP_COMMIT() asm volatile("cp.async.commit_group;" ::: "memory")
#define CP_WAIT0()  asm volatile("cp.async.wait_group 0;" ::: "memory")

__device__ __forceinline__ uint32_t packh2(float a, float b) {
    __half2 h = __floats2half2_rn(a, b);
    return *reinterpret_cast<uint32_t*>(&h);
}

// ---------------------------------------------------------------------------
// Fused prepass: fp32 -> fp16 for x, Wqkv, out_w (one streaming kernel)
// ---------------------------------------------------------------------------
#define S0 ((size_t)SEQ * DMODEL)
#define S1 ((size_t)DMODEL * QKV_N)
#define S2 ((size_t)DMODEL * DMODEL)

__global__ void cvt_all(const float* __restrict__ x, const float* __restrict__ w1,
                        const float* __restrict__ w2,
                        __half* __restrict__ xh, __half* __restrict__ w1h,
                        __half* __restrict__ w2h) {
    size_t i = ((size_t)blockIdx.x * 256 + threadIdx.x) * 4;
    const float* src; __half* dst; size_t off;
    if (i < S0)           { src = x;  dst = xh;  off = i; }
    else if (i < S0 + S1) { src = w1; dst = w1h; off = i - S0; }
    else                  { src = w2; dst = w2h; off = i - S0 - S1; }
    float4 v = *reinterpret_cast<const float4*>(src + off);
    uint2 o;
    o.x = packh2(v.x, v.y);
    o.y = packh2(v.z, v.w);
    *reinterpret_cast<uint2*>(dst + off) = o;
}

// ---------------------------------------------------------------------------
// fp16 tensor GEMM: C[M,N] = A[M,K] @ B[K,N] + bias   (B row-major!)
// 256x128 CTA tile, BK=64, 512 threads (16 warps: 8m x 2n), warp tile 32x64.
// A fragments via ldmatrix, B fragments via ldmatrix.trans (no pre-transpose).
// 2-stage cp.async pipeline, one __syncthreads per k-tile.
// ---------------------------------------------------------------------------
#define BKH 64
#define A_PITCH_B 144                   // bytes per A smem row (128 data + 16 pad)
#define B_PITCH_B 272                   // bytes per B smem row (256 data + 16 pad)
#define A_TILE_B (256 * A_PITCH_B)      // 36864
#define B_TILE_B (64 * B_PITCH_B)       // 17408
#define STG_B (A_TILE_B + B_TILE_B)     // 54272
#define GEMM_SMEM (2 * STG_B)           // 108544

__global__ __launch_bounds__(512, 1) void gemm_h(
    const __half* __restrict__ A, const __half* __restrict__ B,
    const float* __restrict__ bias, __half* __restrict__ Ch,
    float* __restrict__ Cf, int M, int N, int K)
{
    extern __shared__ char sh[];
    const uint32_t sbase = smem_u32(sh);

    const int tid  = threadIdx.x;
    const int warp = tid >> 5;
    const int lane = tid & 31;
    const int gq   = lane >> 2;
    const int kq   = lane & 3;
    const int wm   = warp >> 1;         // 0..7 -> row offset wm*32
    const int wn   = warp & 1;          // 0..1 -> col offset wn*64
    const int row0 = blockIdx.y * 256;
    const int col0 = blockIdx.x * 128;
    const int ntiles = K / BKH;

    // A loads: 2 threads per row (256 rows), 64B each (4 cp16)
    const int lrA = tid >> 1;
    const int lbA = (tid & 1) * 64;     // byte offset in 128B row
    const __half* gA = A + (size_t)(row0 + lrA) * K + (lbA >> 1);
    // B loads: 8 threads per row (64 rows), 32B each (2 cp16)
    const int brB = tid >> 3;
    const int bcB = (tid & 7) * 32;     // byte offset in 256B row
    const __half* gB = B + (size_t)brB * N + col0 + (bcB >> 1);

    // fragment lane addressing (stage-relative byte offsets)
    const uint32_t aRel = (uint32_t)((wm * 32 + (lane & 15)) * A_PITCH_B
                                     + (lane >> 4) * 16);
    const uint32_t bRel = (uint32_t)A_TILE_B
        + (uint32_t)(((lane & 7) + ((lane >> 3) & 1) * 8) * B_PITCH_B
                     + ((lane >> 4) & 1) * 16 + wn * 128);

    float acc[2][8][4];
    #pragma unroll
    for (int mt = 0; mt < 2; mt++)
        #pragma unroll
        for (int nt = 0; nt < 8; nt++)
            #pragma unroll
            for (int i = 0; i < 4; i++) acc[mt][nt][i] = 0.f;

    #define LOAD_TILE(t, s) do {                                                \
        uint32_t base_ = sbase + (uint32_t)(s) * STG_B;                         \
        const __half* a_ = gA + (size_t)(t) * BKH;                              \
        uint32_t da_ = base_ + (uint32_t)(lrA * A_PITCH_B + lbA);               \
        cp16(da_,      a_);      cp16(da_ + 16, a_ + 8);                        \
        cp16(da_ + 32, a_ + 16); cp16(da_ + 48, a_ + 24);                       \
        const __half* b_ = gB + (size_t)(t) * BKH * N;                          \
        uint32_t db_ = base_ + A_TILE_B + (uint32_t)(brB * B_PITCH_B + bcB);    \
        cp16(db_, b_); cp16(db_ + 16, b_ + 8);                                  \
        CP_COMMIT();                                                            \
    } while (0)

    #define COMPUTE(s) do {                                                     \
        uint32_t ab_ = sbase + (uint32_t)(s) * STG_B + aRel;                    \
        uint32_t bb_ = sbase + (uint32_t)(s) * STG_B + bRel;                    \
        _Pragma("unroll")                                                       \
        for (int ks = 0; ks < 4; ks++) {                                        \
            uint32_t af0[4], af1[4];                                            \
            ldmx4(af0, ab_ + ks * 32);                                          \
            ldmx4(af1, ab_ + 16 * A_PITCH_B + ks * 32);                         \
            _Pragma("unroll")                                                   \
            for (int p = 0; p < 4; p++) {                                       \
                uint32_t bf[4];                                                 \
                ldmx4t(bf, bb_ + ks * (16 * B_PITCH_B) + p * 32);               \
                mma_f16(acc[0][2 * p],     af0, bf[0], bf[1]);                  \
                mma_f16(acc[0][2 * p + 1], af0, bf[2], bf[3]);                  \
                mma_f16(acc[1][2 * p],     af1, bf[0], bf[1]);                  \
                mma_f16(acc[1][2 * p + 1], af1, bf[2], bf[3]);                  \
            }                                                                   \
        }                                                                       \
    } while (0)

    LOAD_TILE(0, 0);
    for (int t = 0; t < ntiles; t++) {
        CP_WAIT0();
        __syncthreads();
        if (t + 1 < ntiles) LOAD_TILE(t + 1, (t + 1) & 1);
        COMPUTE(t & 1);
    }

    // ---- epilogue ----
    #pragma unroll
    for (int mt = 0; mt < 2; mt++) {
        int r = row0 + wm * 32 + mt * 16 + gq;
        #pragma unroll
        for (int nt = 0; nt < 8; nt++) {
            int c = col0 + wn * 64 + nt * 8 + kq * 2;
            float b0 = bias[c], b1 = bias[c + 1];
            float v0 = acc[mt][nt][0] + b0, v1 = acc[mt][nt][1] + b1;
            float v2 = acc[mt][nt][2] + b0, v3 = acc[mt][nt][3] + b1;
            if (Ch) {
                *reinterpret_cast<uint32_t*>(&Ch[(size_t)r * N + c]) = packh2(v0, v1);
                *reinterpret_cast<uint32_t*>(&Ch[(size_t)(r + 8) * N + c]) = packh2(v2, v3);
            } else {
                *reinterpret_cast<float2*>(&Cf[(size_t)r * N + c]) = make_float2(v0, v1);
                *reinterpret_cast<float2*>(&Cf[(size_t)(r + 8) * N + c]) = make_float2(v2, v3);
            }
        }
    }
}

// ---------------------------------------------------------------------------
// Flash attention, fp16 MMA (causal + per-head additive key bias).
// BM=128 q-rows, BN=64 keys, DH=128. 8 warps, each owns 16 q-rows.
// P stays in registers. 2-stage cp.async K/V ring, one __syncthreads per kb.
// ---------------------------------------------------------------------------
#define FPITCH 136
#define QTILE_B (128 * FPITCH * 2)      // 34816
#define KTILE_B (64 * FPITCH * 2)       // 17408
#define KVSTG_B (2 * KTILE_B)           // 34816
#define FLASH_SMEM (QTILE_B + 2 * KVSTG_B)

__global__ __launch_bounds__(256, 2) void flash_h(
    const __half* __restrict__ qkv, const float* __restrict__ attn_bias,
    __half* __restrict__ out)
{
    extern __shared__ char fsm[];
    const uint32_t qsb  = smem_u32(fsm);
    const uint32_t kvsb = qsb + QTILE_B;

    const int qb   = (gridDim.x - 1) - blockIdx.x;  // heavy blocks first
    const int h    = blockIdx.y;
    const int tid  = threadIdx.x;
    const int warp = tid >> 5;
    const int lane = tid & 31;
    const int gq   = lane >> 2;
    const int kq   = lane & 3;

    const float scale = 0.08838834764831845f;  // 1/sqrt(128)
    const float* bh = attn_bias + (size_t)h * SEQ;

    const uint32_t qOff = qsb + (uint32_t)((warp * 16 + (lane & 15)) * 272 + (lane >> 4) * 16);
    const int kRow = (lane & 7) + ((lane >> 4) & 1) * 8;
    const uint32_t kRel = (uint32_t)(kRow * 272 + ((lane >> 3) & 1) * 16);
    const int vRow = (lane & 7) + ((lane >> 3) & 1) * 8;
    const uint32_t vRel = (uint32_t)(vRow * 272 + ((lane >> 4) & 1) * 16) + KTILE_B;

    #define LOADKV(kb_, s_) do {                                                \
        uint32_t kvb_ = kvsb + (uint32_t)(s_) * KVSTG_B;                        \
        _Pragma("unroll")                                                       \
        for (int i_ = 0; i_ < 4; i_++) {                                        \
            int idx_ = tid + i_ * 256;                                          \
            int r_ = idx_ >> 4, c_ = idx_ & 15;                                 \
            const __half* kp_ = &qkv[(size_t)((kb_) * 64 + r_) * QKV_N          \
                                     + DMODEL + h * DH + c_ * 8];               \
            uint32_t d_ = kvb_ + (uint32_t)(r_ * 272 + c_ * 16);                \
            cp16(d_, kp_);                                                      \
            cp16(d_ + KTILE_B, kp_ + DMODEL);                                   \
        }                                                                       \
        CP_COMMIT();                                                            \
    } while (0)

    #pragma unroll
    for (int i = 0; i < 8; i++) {
        int idx = tid + i * 256;
        int r = idx >> 4, c = idx & 15;
        cp16(qsb + (uint32_t)(r * 272 + c * 16),
             &qkv[(size_t)(qb * 128 + r) * QKV_N + h * DH + c * 8]);
    }
    LOADKV(0, 0);

    float o[16][4];
    #pragma unroll
    for (int nt = 0; nt < 16; nt++)
        #pragma unroll
        for (int i = 0; i < 4; i++) o[nt][i] = 0.f;
    float m0 = -1e30f, m1 = -1e30f, l0 = 0.f, l1 = 0.f;

    const int qrow0 = qb * 128 + warp * 16 + gq;
    const int nkb = 2 * qb + 2;

    for (int kb = 0; kb < nkb; kb++) {
        CP_WAIT0();
        __syncthreads();
        if (kb + 1 < nkb) LOADKV(kb + 1, (kb + 1) & 1);

        const uint32_t stg = kvsb + (uint32_t)(kb & 1) * KVSTG_B;
        const uint32_t kOff = stg + kRel;
        const uint32_t vOff = stg + vRel;

        float s[8][4];
        #pragma unroll
        for (int nt = 0; nt < 8; nt++)
            #pragma unroll
            for (int i = 0; i < 4; i++) s[nt][i] = 0.f;

        #pragma unroll
        for (int ks = 0; ks < 8; ks++) {
            uint32_t aq[4];
            ldmx4(aq, qOff + ks * 32);
            #pragma unroll
            for (int p = 0; p < 4; p++) {
                uint32_t bf[4];
                ldmx4(bf, kOff + p * (16 * 272) + ks * 32);
                mma_f16(s[2 * p],     aq, bf[0], bf[1]);
                mma_f16(s[2 * p + 1], aq, bf[2], bf[3]);
            }
        }

        const bool diag = (kb >= 2 * qb);
        #pragma unroll
        for (int nt = 0; nt < 8; nt++) {
            int j = nt * 8 + kq * 2;
            float b0v = bh[kb * 64 + j], b1v = bh[kb * 64 + j + 1];
            s[nt][0] = s[nt][0] * scale + b0v;
            s[nt][1] = s[nt][1] * scale + b1v;
            s[nt][2] = s[nt][2] * scale + b0v;
            s[nt][3] = s[nt][3] * scale + b1v;
            if (diag) {
                int jg = kb * 64 + j;
                if (jg     > qrow0)     s[nt][0] = -1e30f;
                if (jg + 1 > qrow0)     s[nt][1] = -1e30f;
                if (jg     > qrow0 + 8) s[nt][2] = -1e30f;
                if (jg + 1 > qrow0 + 8) s[nt][3] = -1e30f;
            }
        }

        float mx0 = -1e30f, mx1 = -1e30f;
        #pragma unroll
        for (int nt = 0; nt < 8; nt++) {
            mx0 = fmaxf(mx0, fmaxf(s[nt][0], s[nt][1]));
            mx1 = fmaxf(mx1, fmaxf(s[nt][2], s[nt][3]));
        }
        mx0 = fmaxf(mx0, __shfl_xor_sync(0xffffffffu, mx0, 1));
        mx0 = fmaxf(mx0, __shfl_xor_sync(0xffffffffu, mx0, 2));
        mx1 = fmaxf(mx1, __shfl_xor_sync(0xffffffffu, mx1, 1));
        mx1 = fmaxf(mx1, __shfl_xor_sync(0xffffffffu, mx1, 2));

        float mn0 = fmaxf(m0, mx0), mn1 = fmaxf(m1, mx1);
        float al0 = __expf(m0 - mn0), al1 = __expf(m1 - mn1);
        m0 = mn0; m1 = mn1;

        float ps0 = 0.f, ps1 = 0.f;
        #pragma unroll
        for (int nt = 0; nt < 8; nt++) {
            s[nt][0] = __expf(s[nt][0] - mn0);
            s[nt][1] = __expf(s[nt][1] - mn0);
            s[nt][2] = __expf(s[nt][2] - mn1);
            s[nt][3] = __expf(s[nt][3] - mn1);
            ps0 += s[nt][0] + s[nt][1];
            ps1 += s[nt][2] + s[nt][3];
        }
        ps0 += __shfl_xor_sync(0xffffffffu, ps0, 1);
        ps0 += __shfl_xor_sync(0xffffffffu, ps0, 2);
        ps1 += __shfl_xor_sync(0xffffffffu, ps1, 1);
        ps1 += __shfl_xor_sync(0xffffffffu, ps1, 2);
        l0 = l0 * al0 + ps0;
        l1 = l1 * al1 + ps1;

        #pragma unroll
        for (int nt = 0; nt < 16; nt++) {
            o[nt][0] *= al0; o[nt][1] *= al0;
            o[nt][2] *= al1; o[nt][3] *= al1;
        }

        #pragma unroll
        for (int ks = 0; ks < 4; ks++) {
            uint32_t ap[4];
            ap[0] = packh2(s[2 * ks][0],     s[2 * ks][1]);
            ap[1] = packh2(s[2 * ks][2],     s[2 * ks][3]);
            ap[2] = packh2(s[2 * ks + 1][0], s[2 * ks + 1][1]);
            ap[3] = packh2(s[2 * ks + 1][2], s[2 * ks + 1][3]);
            #pragma unroll
            for (int p = 0; p < 8; p++) {
                uint32_t bf[4];
                ldmx4t(bf, vOff + ks * (16 * 272) + p * 32);
                mma_f16(o[2 * p],     ap, bf[0], bf[1]);
                mma_f16(o[2 * p + 1], ap, bf[2], bf[3]);
            }
        }
    }

    float il0 = 1.f / l0, il1 = 1.f / l1;
    int r = qb * 128 + warp * 16 + gq;
    #pragma unroll
    for (int nt = 0; nt < 16; nt++) {
        int c = h * DH + nt * 8 + kq * 2;
        *reinterpret_cast<uint32_t*>(&out[(size_t)r * DMODEL + c]) =
            packh2(o[nt][0] * il0, o[nt][1] * il0);
        *reinterpret_cast<uint32_t*>(&out[(size_t)(r + 8) * DMODEL + c]) =
            packh2(o[nt][2] * il1, o[nt][3] * il1);
    }
}

// ---------------------------------------------------------------------------
// kernel_launch
// ---------------------------------------------------------------------------
extern "C" void kernel_launch(void* const* d_in, const int* in_sizes, int n_in,
                              void* d_out, int out_size)
{
    (void)in_sizes; (void)n_in; (void)out_size;
    const float* x         = (const float*)d_in[0];
    const float* Wqkv      = (const float*)d_in[1];
    const float* Wqkv_bias = (const float*)d_in[2];
    const float* out_w     = (const float*)d_in[3];
    const float* out_b     = (const float*)d_in[4];
    const float* attn_bias = (const float*)d_in[5];
    float* out = (float*)d_out;

    __half *xh, *wqkvh, *wouth, *qkv, *attn;
    cudaGetSymbolAddress((void**)&xh,    g_xh);
    cudaGetSymbolAddress((void**)&wqkvh, g_wqkvh);
    cudaGetSymbolAddress((void**)&wouth, g_wouth);
    cudaGetSymbolAddress((void**)&qkv,   g_qkv);
    cudaGetSymbolAddress((void**)&attn,  g_attn);

    cudaFuncSetAttribute(gemm_h, cudaFuncAttributeMaxDynamicSharedMemorySize,
                         GEMM_SMEM);
    cudaFuncSetAttribute(flash_h, cudaFuncAttributeMaxDynamicSharedMemorySize,
                         FLASH_SMEM);

    // 0) fused prepass: fp32 -> fp16 (no transposes; B consumed row-major)
    cvt_all<<<(int)((S0 + S1 + S2) / 1024), 256>>>(x, Wqkv, out_w, xh, wqkvh, wouth);

    // 1) QKV projection -> fp16 qkv   [2048,2048]@[2048,6144]
    gemm_h<<<dim3(QKV_N / 128, SEQ / 256), 512, GEMM_SMEM>>>(
        xh, wqkvh, Wqkv_bias, qkv, nullptr, SEQ, QKV_N, DMODEL);

    // 2) Flash attention -> fp16 attn
    flash_h<<<dim3(SEQ / 128, NH), 256, FLASH_SMEM>>>(qkv, attn_bias, attn);

    // 3) Output projection -> fp32 out   [2048,2048]@[2048,2048]
    gemm_h<<<dim3(DMODEL / 128, SEQ / 256), 512, GEMM_SMEM>>>(
        attn, wouth, out_b, nullptr, out, SEQ, DMODEL, DMODEL);
}